// round 17
// baseline (speedup 1.0000x reference)
#include <cuda_runtime.h>
#include <cstdint>

// LSTM: B x T x I -> last hidden -> FC.  I=4, H=8, O=1, T=512.
// Round-17 = R15 structure with the 4 legacy HMMAs replaced by a
// shuffle+HFMA2 ladder. Theory: sm_103a mma.sync (legacy HMMA) has ~150-200
// cyc dependent latency / ~30 cyc/op SMSP throughput (fits R12-R16), while
// HFMA2 is lat-4/rt-2. Same thread layout (thread = batch grp, units 2q,2q+1):
//   * 4x width-4 SHFL gather the batch's h pairs (one 26-cyc level)
//   * 8x PRMT duplicate into (h_k,h_k) half2
//   * per gate: 8 HFMA2 seeded by the precomputed input projection (even/odd
//     split, 4 deep) + HADD2
// Tail (f16 c, tanh.approx.f16x2), IP prefetch, FC head identical to R15
// (rel_err 2.40e-4 measured). 1024 warps, 8 batches/warp.

#define T_SEQ 512
#define IDIM  4
#define HDIM  8

__device__ __forceinline__ uint32_t cvt_f16x2(float hi, float lo) {
    uint32_t r; asm("cvt.rn.f16x2.f32 %0, %1, %2;" : "=r"(r) : "f"(hi), "f"(lo)); return r;
}
__device__ __forceinline__ uint32_t htanh2(uint32_t a) {
    uint32_t d; asm("tanh.approx.f16x2 %0,%1;" : "=r"(d) : "r"(a)); return d;
}
__device__ __forceinline__ uint32_t hfma2(uint32_t a, uint32_t b, uint32_t c) {
    uint32_t d; asm("fma.rn.f16x2 %0,%1,%2,%3;" : "=r"(d) : "r"(a), "r"(b), "r"(c)); return d;
}
__device__ __forceinline__ uint32_t hmul2(uint32_t a, uint32_t b) {
    uint32_t d; asm("mul.rn.f16x2 %0,%1,%2;" : "=r"(d) : "r"(a), "r"(b)); return d;
}
__device__ __forceinline__ uint32_t hadd2v(uint32_t a, uint32_t b) {
    uint32_t d; asm("add.rn.f16x2 %0,%1,%2;" : "=r"(d) : "r"(a), "r"(b)); return d;
}
__device__ __forceinline__ float2 cvt_f32x2(uint32_t p) {   // (lo, hi)
    float lo, hi;
    asm("{ .reg .f16 l, h; mov.b32 {l, h}, %2;"
        "  cvt.f32.f16 %0, l; cvt.f32.f16 %1, h; }"
        : "=f"(lo), "=f"(hi) : "r"(p));
    return make_float2(lo, hi);
}

__global__ __launch_bounds__(32)
void lstm_ladder_kernel(const float* __restrict__ x,
                        const float* __restrict__ W_ih,
                        const float* __restrict__ W_hh,
                        const float* __restrict__ b_ih,
                        const float* __restrict__ b_hh,
                        const float* __restrict__ W_fc,
                        const float* __restrict__ b_fc,
                        float* __restrict__ out,
                        int B)
{
    const int lane = threadIdx.x & 31;
    const int grp  = lane >> 2;                     // batch row within warp
    const int q    = lane & 3;                      // unit-pair selector (units 2q, 2q+1)

    const int base = blockIdx.x * 8;                // 8 batch rows per warp
    const int r0 = base + grp;
    const bool v0 = (r0 < B);
    const int r0c = v0 ? r0 : (B - 1);

    // ---- recurrent weights: whh[gt][k] = (s*W_hh[u0,k], s*W_hh[u1,k]) f16x2 ----
    // sigmoid gates (i,f,o) pre-scaled by 0.5 so sigmoid(z) = 0.5*tanh(acc)+0.5
    uint32_t whh[4][HDIM];
    uint32_t wih[4][IDIM], bias[4];
    {
        const int u0 = 2 * q, u1 = 2 * q + 1;
#pragma unroll
        for (int gt = 0; gt < 4; ++gt) {
            const float s = (gt == 2) ? 1.0f : 0.5f;
            const int ra = gt * HDIM + u0, rb = gt * HDIM + u1;
#pragma unroll
            for (int k = 0; k < HDIM; ++k)
                whh[gt][k] = cvt_f16x2(s * W_hh[rb * HDIM + k],
                                       s * W_hh[ra * HDIM + k]);
#pragma unroll
            for (int k = 0; k < IDIM; ++k)
                wih[gt][k] = cvt_f16x2(s * W_ih[rb * IDIM + k],
                                       s * W_ih[ra * IDIM + k]);
            bias[gt] = cvt_f16x2(s * (b_ih[rb] + b_hh[rb]),
                                 s * (b_ih[ra] + b_hh[ra]));
        }
    }

    const float4* __restrict__ xp0 =
        reinterpret_cast<const float4*>(x) + (size_t)r0c * T_SEQ;

    const uint32_t K05 = 0x38003800u;               // (0.5, 0.5) half2

    // state: h pair (units 2q,2q+1) f16x2; c pair f16x2
    uint32_t a0 = 0u;
    uint32_t c16 = 0u;

    // IP(t) = x_t @ W_ih^T + bias (f16x2 per gate, unit-pair layout)
    auto ip_build = [&](const float4 xv, uint32_t (&ip)[4]) {
        const uint32_t d0 = cvt_f16x2(xv.x, xv.x), d1 = cvt_f16x2(xv.y, xv.y);
        const uint32_t d2 = cvt_f16x2(xv.z, xv.z), d3 = cvt_f16x2(xv.w, xv.w);
#pragma unroll
        for (int gt = 0; gt < 4; ++gt) {
            uint32_t p = hfma2(d0, wih[gt][0], bias[gt]);
            p = hfma2(d1, wih[gt][1], p);
            p = hfma2(d2, wih[gt][2], p);
            ip[gt] = hfma2(d3, wih[gt][3], p);
        }
    };

    // rolling 4-step x prefetch
    float4 b0[4];
#pragma unroll
    for (int i = 0; i < 4; ++i) b0[i] = xp0[i];

    uint32_t ip[4];
    ip_build(b0[0], ip);

#pragma unroll 1
    for (int t0 = 0; t0 < T_SEQ; t0 += 4) {
        const int tn = (t0 + 4) & (T_SEQ - 1);
        float4 n0[4];
#pragma unroll
        for (int i = 0; i < 4; ++i) n0[i] = xp0[tn + i];

#pragma unroll
        for (int u = 0; u < 4; ++u) {
            // build IP(t+1) off-chain
            uint32_t ipn[4];
            ip_build((u < 3) ? b0[u + 1] : n0[0], ipn);

            // ---- gather my batch's 4 h-pairs (one shfl level) ----
            const uint32_t hp0 = __shfl_sync(0xffffffffu, a0, 0, 4);
            const uint32_t hp1 = __shfl_sync(0xffffffffu, a0, 1, 4);
            const uint32_t hp2 = __shfl_sync(0xffffffffu, a0, 2, 4);
            const uint32_t hp3 = __shfl_sync(0xffffffffu, a0, 3, 4);
            // duplicate to (h_k, h_k)
            uint32_t hd[8];
            hd[0] = __byte_perm(hp0, hp0, 0x1010);  hd[1] = __byte_perm(hp0, hp0, 0x3232);
            hd[2] = __byte_perm(hp1, hp1, 0x1010);  hd[3] = __byte_perm(hp1, hp1, 0x3232);
            hd[4] = __byte_perm(hp2, hp2, 0x1010);  hd[5] = __byte_perm(hp2, hp2, 0x3232);
            hd[6] = __byte_perm(hp3, hp3, 0x1010);  hd[7] = __byte_perm(hp3, hp3, 0x3232);

            // ---- recurrent ladders: z[gt] = IP[gt] + sum_k whh[gt][k] * h_k ----
            uint32_t z[4];
#pragma unroll
            for (int gt = 0; gt < 4; ++gt) {
                uint32_t p = hfma2(whh[gt][0], hd[0], ip[gt]);
                p = hfma2(whh[gt][2], hd[2], p);
                p = hfma2(whh[gt][4], hd[4], p);
                p = hfma2(whh[gt][6], hd[6], p);
                uint32_t r = hmul2(whh[gt][1], hd[1]);
                r = hfma2(whh[gt][3], hd[3], r);
                r = hfma2(whh[gt][5], hd[5], r);
                r = hfma2(whh[gt][7], hd[7], r);
                z[gt] = hadd2v(p, r);
            }

            // ---- all-f16 tail: activations + cell + hidden (R15 recipe) ----
            const uint32_t sI = hfma2(htanh2(z[0]), K05, K05);   // i
            const uint32_t sF = hfma2(htanh2(z[1]), K05, K05);   // f
            const uint32_t tG = htanh2(z[2]);                    // g
            const uint32_t sO = hfma2(htanh2(z[3]), K05, K05);   // o

            c16 = hfma2(sF, c16, hmul2(sI, tG));    // c = f*c + i*g (fp16)
            a0  = hmul2(sO, htanh2(c16));           // h = o * tanh(c)

#pragma unroll
            for (int gt = 0; gt < 4; ++gt) ip[gt] = ipn[gt];
        }

#pragma unroll
        for (int i = 0; i < 4; ++i) b0[i] = n0[i];
    }

    // ---- FC head: out[b] = sum_u h[b,u] * W_fc[u] + b_fc ----
    const float w0 = __ldg(W_fc + 2 * q);
    const float w1 = __ldg(W_fc + 2 * q + 1);
    const float2 h0 = cvt_f32x2(a0);
    float v0r = h0.x * w0 + h0.y * w1;
    v0r += __shfl_xor_sync(0xffffffffu, v0r, 1, 4);
    v0r += __shfl_xor_sync(0xffffffffu, v0r, 2, 4);

    if (q == 0 && v0) out[r0] = v0r + __ldg(b_fc);
}

extern "C" void kernel_launch(void* const* d_in, const int* in_sizes, int n_in,
                              void* d_out, int out_size)
{
    const float* x    = (const float*)d_in[0];
    const float* W_ih = (const float*)d_in[1];
    const float* W_hh = (const float*)d_in[2];
    const float* b_ih = (const float*)d_in[3];
    const float* b_hh = (const float*)d_in[4];
    const float* W_fc = (const float*)d_in[5];
    const float* b_fc = (const float*)d_in[6];
    float* out = (float*)d_out;

    const int B = in_sizes[0] / (T_SEQ * IDIM);     // 8192 here
    const int grid = (B + 7) / 8;                   // one warp per 8 batches

    lstm_ladder_kernel<<<grid, 32>>>(x, W_ih, W_hh, b_ih, b_hh, W_fc, b_fc, out, B);
}